// round 15
// baseline (speedup 1.0000x reference)
#include <cuda_runtime.h>
#include <cuda_fp16.h>
#include <cstdint>
#include <type_traits>

#define NN 50000
#define DD 128
#define K2 256
#define EE 800000
#define EPS 1e-5f
#define CSRG 592            // persistent CSR grid (<= 148*8 co-resident @256thr)
#define NSCB 196            // ceil(NN/256) scan blocks

// ---------------- scratch (device globals) ----------------------------------
__device__ float  g_agg[NN * DD];
__device__ __half g_h0[NN * DD];
__device__ __half g_h1[NN * DD];
__device__ uint32_t g_WtHh[3 * 128 * DD];
__device__ uint32_t g_WtHl[3 * 128 * DD];
__device__ float  g_stats3[3][2 * DD];   // per-layer raw [sum | sumsq]
__device__ int    g_deg[NN];
__device__ int    g_rowptr[NN + 1];
__device__ int    g_cursor[NN];
__device__ int    g_col[EE];
__device__ int    g_bsum[256];
__device__ int    g_bar;

// ---------------- weight prep + zero stats + zero barrier --------------------
__global__ void prep_w_all(const float* __restrict__ Wl0, const float* __restrict__ Wr0,
                           const float* __restrict__ Wl1, const float* __restrict__ Wr1,
                           const float* __restrict__ Wl2, const float* __restrict__ Wr2) {
    int i = blockIdx.x * blockDim.x + threadIdx.x;
    if (i == 0) g_bar = 0;
    if (i < 6 * DD) ((float*)g_stats3)[i] = 0.f;
    if (i >= 3 * 128 * DD) return;
    int L = i / (128 * DD);
    int rem = i - L * (128 * DD);
    int p = rem >> 7, n = rem & 127;
    const float* Wl = (L == 0) ? Wl0 : (L == 1 ? Wl1 : Wl2);
    const float* Wr = (L == 0) ? Wr0 : (L == 1 ? Wr1 : Wr2);
    int k0 = 2 * p;
    float w0, w1;
    if (k0 < DD) {
        w0 = __ldg(&Wl[n * DD + k0]);
        w1 = __ldg(&Wl[n * DD + k0 + 1]);
    } else {
        w0 = __ldg(&Wr[n * DD + (k0 - DD)]);
        w1 = __ldg(&Wr[n * DD + (k0 - DD) + 1]);
    }
    __half h0 = __float2half_rn(w0);
    __half h1 = __float2half_rn(w1);
    __half l0 = __float2half_rn(w0 - __half2float(h0));
    __half l1 = __float2half_rn(w1 - __half2float(h1));
    __half2 hh = __halves2half2(h0, h1);
    __half2 ll = __halves2half2(l0, l1);
    g_WtHh[i] = *reinterpret_cast<uint32_t*>(&hh);
    g_WtHl[i] = *reinterpret_cast<uint32_t*>(&ll);
}

// ---------------- persistent CSR build: zero -> count -> scan -> fill --------
__global__ __launch_bounds__(256)
void csr_kernel(const int* __restrict__ ei, int E) {
    int tid = threadIdx.x, b = blockIdx.x;
    int gtid = b * 256 + tid;
    int nth = gridDim.x * 256;
    int lane = tid & 31, wid = tid >> 5;
    __shared__ int wsum[8];
    __shared__ int s_off;

    auto gbar = [&](int target) {
        __syncthreads();
        if (tid == 0) {
            __threadfence();
            atomicAdd(&g_bar, 1);
            while (atomicAdd(&g_bar, 0) < target) {
                asm volatile("nanosleep.u32 128;");
            }
        }
        __syncthreads();
    };

    // P0: zero degree
    for (int i = gtid; i < NN / 4; i += nth) ((int4*)g_deg)[i] = make_int4(0, 0, 0, 0);
    gbar((int)gridDim.x);

    // P1: count
    for (int e = gtid; e < E; e += nth) {
        int d = __ldg(&ei[E + e]);
        if (d >= 0 && d < NN) atomicAdd(&g_deg[d], 1);
    }
    gbar(2 * (int)gridDim.x);

    // P2a: block-local scan (blocks [0, NSCB))
    int idx = 0, v = 0, excl = 0;
    if (b < NSCB) {
        idx = b * 256 + tid;
        v = (idx < NN) ? g_deg[idx] : 0;
        int incl = v;
#pragma unroll
        for (int off = 1; off < 32; off <<= 1) {
            int y = __shfl_up_sync(0xffffffffu, incl, off);
            if (lane >= off) incl += y;
        }
        if (lane == 31) wsum[wid] = incl;
        __syncthreads();
        if (tid == 0) {
            int s = 0;
#pragma unroll
            for (int w = 0; w < 8; w++) { int t2 = wsum[w]; wsum[w] = s; s += t2; }
            g_bsum[b] = s;
        }
        __syncthreads();
        excl = wsum[wid] + incl - v;
    }
    gbar(3 * (int)gridDim.x);

    // P2b: global offsets + rowptr/cursor
    if (b < NSCB) {
        if (tid == 0) {
            int off = 0;
            for (int j = 0; j < b; j++) off += g_bsum[j];
            s_off = off;
        }
        __syncthreads();
        if (idx < NN) {
            int r = s_off + excl;
            g_rowptr[idx] = r;
            g_cursor[idx] = r;
        }
        if (b == NSCB - 1 && tid == 0) g_rowptr[NN] = s_off + g_bsum[b];
    }
    gbar(4 * (int)gridDim.x);

    // P3: fill
    for (int e = gtid; e < E; e += nth) {
        int s = __ldg(&ei[e]);
        int d = __ldg(&ei[E + e]);
        if (d >= 0 && d < NN) {
            int pos = atomicAdd(&g_cursor[d], 1);
            g_col[pos] = s;
        }
    }
}

// ---------------- gather (fp32 input, layer 0), predicated batches -----------
__global__ void gather_f32(const float* __restrict__ x) {
    int w = (blockIdx.x * blockDim.x + threadIdx.x) >> 5;
    int lane = threadIdx.x & 31;
    if (w >= NN) return;
    int start = __ldg(&g_rowptr[w]), end = __ldg(&g_rowptr[w + 1]);
    float4 acc = make_float4(0.f, 0.f, 0.f, 0.f);
    for (int i = start; i < end; i += 8) {
        int sidx[8];
        bool ok[8];
#pragma unroll
        for (int u = 0; u < 8; u++) {
            int j = i + u;
            ok[u] = j < end;
            sidx[u] = __ldg(&g_col[ok[u] ? j : start]);
        }
        float4 vv[8];
#pragma unroll
        for (int u = 0; u < 8; u++)
            vv[u] = __ldg((const float4*)(x + (size_t)sidx[u] * DD) + lane);
#pragma unroll
        for (int u = 0; u < 8; u++) {
            if (ok[u]) {
                acc.x += vv[u].x; acc.y += vv[u].y;
                acc.z += vv[u].z; acc.w += vv[u].w;
            }
        }
    }
    float sc = 1.0f / fmaxf((float)(end - start), 1.0f);
    acc.x *= sc; acc.y *= sc; acc.z *= sc; acc.w *= sc;
    ((float4*)(g_agg + (size_t)w * DD))[lane] = acc;
}

// ---------------- gather (fp16 + fused BN+ReLU), block-local affine ----------
__global__ void gather_f16(const __half* __restrict__ x,
                           const float* __restrict__ prev_stats,
                           const float* __restrict__ prev_gamma,
                           const float* __restrict__ prev_beta) {
    __shared__ float sc_s[128];
    __shared__ float sh_s[128];
    if (threadIdx.x < 128) {
        int c = threadIdx.x;
        float m = __ldg(&prev_stats[c]) * (1.0f / NN);
        float var = __ldg(&prev_stats[DD + c]) * (1.0f / NN) - m * m;
        float s = __ldg(&prev_gamma[c]) * rsqrtf(var + EPS);
        sc_s[c] = s;
        sh_s[c] = __ldg(&prev_beta[c]) - m * s;
    }
    __syncthreads();
    int w = (blockIdx.x * blockDim.x + threadIdx.x) >> 5;
    int lane = threadIdx.x & 31;
    if (w >= NN) return;
    float4 s4 = ((const float4*)sc_s)[lane];
    float4 b4 = ((const float4*)sh_s)[lane];
    int start = __ldg(&g_rowptr[w]), end = __ldg(&g_rowptr[w + 1]);
    float4 acc = make_float4(0.f, 0.f, 0.f, 0.f);

    for (int i = start; i < end; i += 8) {
        int sidx[8];
        bool ok[8];
#pragma unroll
        for (int u = 0; u < 8; u++) {
            int j = i + u;
            ok[u] = j < end;
            sidx[u] = __ldg(&g_col[ok[u] ? j : start]);
        }
        uint2 rr[8];
#pragma unroll
        for (int u = 0; u < 8; u++)
            rr[u] = __ldg((const uint2*)(x + (size_t)sidx[u] * DD) + lane);
#pragma unroll
        for (int u = 0; u < 8; u++) {
            __half2 h0 = *reinterpret_cast<__half2*>(&rr[u].x);
            __half2 h1 = *reinterpret_cast<__half2*>(&rr[u].y);
            float2 f0 = __half22float2(h0);
            float2 f1 = __half22float2(h1);
            if (ok[u]) {
                acc.x += fmaxf(fmaf(f0.x, s4.x, b4.x), 0.f);
                acc.y += fmaxf(fmaf(f0.y, s4.y, b4.y), 0.f);
                acc.z += fmaxf(fmaf(f1.x, s4.z, b4.z), 0.f);
                acc.w += fmaxf(fmaf(f1.y, s4.w, b4.w), 0.f);
            }
        }
    }
    float sc = 1.0f / fmaxf((float)(end - start), 1.0f);
    acc.x *= sc; acc.y *= sc; acc.z *= sc; acc.w *= sc;
    ((float4*)(g_agg + (size_t)w * DD))[lane] = acc;
}

// ---------------- GEMM: fp16 hi/lo 3-term ------------------------------------
#define AHSTRIDE 12
#define BHSTRIDE 136

__device__ __forceinline__ void split_f16x2(float a, float b, uint32_t& hi, uint32_t& lo) {
    __half ha = __float2half_rn(a), hb = __float2half_rn(b);
    __half la = __float2half_rn(a - __half2float(ha));
    __half lb = __float2half_rn(b - __half2float(hb));
    __half2 h = __halves2half2(ha, hb);
    __half2 l = __halves2half2(la, lb);
    hi = *reinterpret_cast<uint32_t*>(&h);
    lo = *reinterpret_cast<uint32_t*>(&l);
}

__device__ __forceinline__ void mma_f16(float* d, uint32_t a0, uint32_t a1,
                                        uint32_t a2, uint32_t a3,
                                        uint32_t b0, uint32_t b1) {
    asm volatile(
        "mma.sync.aligned.m16n8k16.row.col.f32.f16.f16.f32 "
        "{%0,%1,%2,%3},{%4,%5,%6,%7},{%8,%9},{%0,%1,%2,%3};"
        : "+f"(d[0]), "+f"(d[1]), "+f"(d[2]), "+f"(d[3])
        : "r"(a0), "r"(a1), "r"(a2), "r"(a3), "r"(b0), "r"(b1));
}

template <typename TI, int XFORM, typename TO>
__global__ __launch_bounds__(128, 2)
void gemm_kernel(const TI* __restrict__ Xin,
                 const uint32_t* __restrict__ WtHh,
                 const uint32_t* __restrict__ WtHl,
                 const float* __restrict__ bias,
                 const float* __restrict__ prev_stats,
                 const float* __restrict__ prev_gamma,
                 const float* __restrict__ prev_beta,
                 float* __restrict__ cur_stats,
                 TO* __restrict__ Y) {
    constexpr bool USE_H = std::is_same_v<TI, __half>;

    __shared__ __align__(16) uint32_t AshH[128 * AHSTRIDE];
    __shared__ __align__(16) uint32_t AshL[128 * AHSTRIDE];
    __shared__ __align__(16) uint32_t BshH[8 * BHSTRIDE];
    __shared__ __align__(16) uint32_t BshL[8 * BHSTRIDE];
    __shared__ float bias_s[128];
    __shared__ float sc_s[128];
    __shared__ float sh_s[128];

    int tid = threadIdx.x;
    int brow = blockIdx.x * 128;
    int wid = tid >> 5, lane = tid & 31;
    int group = lane >> 2, tg = lane & 3;
    int warp_m = (wid >> 1) * 64, warp_n = (wid & 1) * 64;

    if (tid < 128) {
        bias_s[tid] = __ldg(&bias[tid]);
        if (XFORM) {
            float m = __ldg(&prev_stats[tid]) * (1.0f / NN);
            float var = __ldg(&prev_stats[DD + tid]) * (1.0f / NN) - m * m;
            float s = __ldg(&prev_gamma[tid]) * rsqrtf(var + EPS);
            sc_s[tid] = s;
            sh_s[tid] = __ldg(&prev_beta[tid]) - m * s;
        }
    }
    __syncthreads();

    float acc[4][8][4];
#pragma unroll
    for (int mt = 0; mt < 4; mt++)
#pragma unroll
        for (int nt = 0; nt < 8; nt++)
#pragma unroll
            for (int c = 0; c < 4; c++) acc[mt][nt][c] = 0.f;

    float4 pa[4];
    uint2 pbh[4], pbl[4];

    auto load_tiles = [&](int kc) {
#pragma unroll
        for (int i = 0; i < 4; i++) {
            int l = tid + i * 128;
            int row = l >> 2, kq = l & 3;
            int r = brow + row;
            float4 v = make_float4(0.f, 0.f, 0.f, 0.f);
            if (r < NN) {
                if (kc < DD) {
                    v = __ldg((const float4*)(g_agg + (size_t)r * DD + kc) + kq);
                } else {
                    int kg = (kc - DD) + kq * 4;
                    if constexpr (USE_H) {
                        uint2 raw = __ldg((const uint2*)(Xin + (size_t)r * DD + kg));
                        __half2 ha = *reinterpret_cast<__half2*>(&raw.x);
                        __half2 hb = *reinterpret_cast<__half2*>(&raw.y);
                        float2 f0 = __half22float2(ha);
                        float2 f1 = __half22float2(hb);
                        v = make_float4(f0.x, f0.y, f1.x, f1.y);
                    } else {
                        v = __ldg((const float4*)(Xin + (size_t)r * DD + kg));
                    }
                    if (XFORM) {
                        float4 s4 = *(const float4*)(sc_s + kg);
                        float4 b4 = *(const float4*)(sh_s + kg);
                        v.x = fmaxf(fmaf(v.x, s4.x, b4.x), 0.f);
                        v.y = fmaxf(fmaf(v.y, s4.y, b4.y), 0.f);
                        v.z = fmaxf(fmaf(v.z, s4.z, b4.z), 0.f);
                        v.w = fmaxf(fmaf(v.w, s4.w, b4.w), 0.f);
                    }
                }
            }
            pa[i] = v;
        }
        int p0 = kc >> 1;
#pragma unroll
        for (int i = 0; i < 4; i++) {
            int l = tid + i * 128;
            int p = l >> 6, j2 = l & 63;
            pbh[i] = ((const uint2*)WtHh)[(size_t)(p0 + p) * 64 + j2];
            pbl[i] = ((const uint2*)WtHl)[(size_t)(p0 + p) * 64 + j2];
        }
    };

    auto store_tiles = [&]() {
#pragma unroll
        for (int i = 0; i < 4; i++) {
            int l = tid + i * 128;
            int row = l >> 2, kq = l & 3;
            uint32_t h0, l0, h1, l1;
            split_f16x2(pa[i].x, pa[i].y, h0, l0);
            split_f16x2(pa[i].z, pa[i].w, h1, l1);
            *(uint2*)&AshH[row * AHSTRIDE + kq * 2] = make_uint2(h0, h1);
            *(uint2*)&AshL[row * AHSTRIDE + kq * 2] = make_uint2(l0, l1);
        }
#pragma unroll
        for (int i = 0; i < 4; i++) {
            int l = tid + i * 128;
            int p = l >> 6, j2 = l & 63;
            *(uint2*)&BshH[p * BHSTRIDE + j2 * 2] = pbh[i];
            *(uint2*)&BshL[p * BHSTRIDE + j2 * 2] = pbl[i];
        }
    };

    load_tiles(0);

    for (int kc = 0; kc < K2; kc += 16) {
        store_tiles();
        __syncthreads();
        if (kc + 16 < K2) load_tiles(kc + 16);

        uint32_t fbh0[8], fbh1[8], fbl0[8], fbl1[8];
#pragma unroll
        for (int nt = 0; nt < 8; nt++) {
            int n = warp_n + nt * 8 + group;
            fbh0[nt] = BshH[tg * BHSTRIDE + n];
            fbh1[nt] = BshH[(tg + 4) * BHSTRIDE + n];
            fbl0[nt] = BshL[tg * BHSTRIDE + n];
            fbl1[nt] = BshL[(tg + 4) * BHSTRIDE + n];
        }
#pragma unroll
        for (int mt = 0; mt < 4; mt++) {
            int m = warp_m + mt * 16;
            uint32_t ah0 = AshH[(m + group) * AHSTRIDE + tg];
            uint32_t ah1 = AshH[(m + group + 8) * AHSTRIDE + tg];
            uint32_t ah2 = AshH[(m + group) * AHSTRIDE + tg + 4];
            uint32_t ah3 = AshH[(m + group + 8) * AHSTRIDE + tg + 4];
            uint32_t al0 = AshL[(m + group) * AHSTRIDE + tg];
            uint32_t al1 = AshL[(m + group + 8) * AHSTRIDE + tg];
            uint32_t al2 = AshL[(m + group) * AHSTRIDE + tg + 4];
            uint32_t al3 = AshL[(m + group + 8) * AHSTRIDE + tg + 4];
#pragma unroll
            for (int nt = 0; nt < 8; nt++) {
                mma_f16(acc[mt][nt], ah0, ah1, ah2, ah3, fbh0[nt], fbh1[nt]);
                mma_f16(acc[mt][nt], al0, al1, al2, al3, fbh0[nt], fbh1[nt]);
                mma_f16(acc[mt][nt], ah0, ah1, ah2, ah3, fbl0[nt], fbl1[nt]);
            }
        }
        __syncthreads();
    }

    // ---- epilogue: bias + store + fused BN partial stats ----
    float cs[16], cq[16];
#pragma unroll
    for (int i = 0; i < 16; i++) { cs[i] = 0.f; cq[i] = 0.f; }

#pragma unroll
    for (int mt = 0; mt < 4; mt++) {
        int r0 = brow + warp_m + mt * 16 + group;
        int r1 = r0 + 8;
#pragma unroll
        for (int nt = 0; nt < 8; nt++) {
            int c = warp_n + nt * 8 + 2 * tg;
            float b0 = bias_s[c], b1 = bias_s[c + 1];
            float o0 = acc[mt][nt][0] + b0, o1 = acc[mt][nt][1] + b1;
            float o2 = acc[mt][nt][2] + b0, o3 = acc[mt][nt][3] + b1;
            if (r0 < NN) {
                if constexpr (std::is_same_v<TO, __half>) {
                    *(__half2*)(Y + (size_t)r0 * DD + c) = __floats2half2_rn(o0, o1);
                } else {
                    *(float2*)(Y + (size_t)r0 * DD + c) = make_float2(o0, o1);
                }
                cs[nt * 2 + 0] += o0; cq[nt * 2 + 0] += o0 * o0;
                cs[nt * 2 + 1] += o1; cq[nt * 2 + 1] += o1 * o1;
            }
            if (r1 < NN) {
                if constexpr (std::is_same_v<TO, __half>) {
                    *(__half2*)(Y + (size_t)r1 * DD + c) = __floats2half2_rn(o2, o3);
                } else {
                    *(float2*)(Y + (size_t)r1 * DD + c) = make_float2(o2, o3);
                }
                cs[nt * 2 + 0] += o2; cq[nt * 2 + 0] += o2 * o2;
                cs[nt * 2 + 1] += o3; cq[nt * 2 + 1] += o3 * o3;
            }
        }
    }
#pragma unroll
    for (int i = 0; i < 16; i++) {
#pragma unroll
        for (int off = 4; off < 32; off <<= 1) {
            cs[i] += __shfl_xor_sync(0xffffffffu, cs[i], off);
            cq[i] += __shfl_xor_sync(0xffffffffu, cq[i], off);
        }
    }
    if (group == 0) {
#pragma unroll
        for (int i = 0; i < 16; i++) {
            int c = warp_n + (i >> 1) * 8 + 2 * tg + (i & 1);
            atomicAdd(&cur_stats[c], cs[i]);
            atomicAdd(&cur_stats[DD + c], cq[i]);
        }
    }
}

// ---------------- final BN apply (block-local affine) ------------------------
__global__ void apply_kernel(float* __restrict__ Y,
                             const float* __restrict__ stats,
                             const float* __restrict__ gamma,
                             const float* __restrict__ beta) {
    __shared__ float sc_s[128];
    __shared__ float sh_s[128];
    if (threadIdx.x < 128) {
        int c = threadIdx.x;
        float m = __ldg(&stats[c]) * (1.0f / NN);
        float var = __ldg(&stats[DD + c]) * (1.0f / NN) - m * m;
        float sc = __ldg(&gamma[c]) * rsqrtf(var + EPS);
        sc_s[c] = sc;
        sh_s[c] = __ldg(&beta[c]) - m * sc;
    }
    __syncthreads();
    int i = blockIdx.x * blockDim.x + threadIdx.x;
    if (i >= NN * (DD / 4)) return;
    float4 v = ((float4*)Y)[i];
    int c = (i & (DD / 4 - 1)) * 4;
    float4 s4 = *(const float4*)(sc_s + c);
    float4 b4 = *(const float4*)(sh_s + c);
    v.x = fmaf(v.x, s4.x, b4.x);
    v.y = fmaf(v.y, s4.y, b4.y);
    v.z = fmaf(v.z, s4.z, b4.z);
    v.w = fmaf(v.w, s4.w, b4.w);
    ((float4*)Y)[i] = v;
}

// ---------------- launch ----------------------------------------------------
extern "C" void kernel_launch(void* const* d_in, const int* in_sizes, int n_in,
                              void* d_out, int out_size) {
    const float* x = (const float*)d_in[0];
    const int* ei = (const int*)d_in[1];
    const float* Wl[3] = {(const float*)d_in[2], (const float*)d_in[7], (const float*)d_in[12]};
    const float* bl[3] = {(const float*)d_in[3], (const float*)d_in[8], (const float*)d_in[13]};
    const float* Wr[3] = {(const float*)d_in[4], (const float*)d_in[9], (const float*)d_in[14]};
    const float* gm[3] = {(const float*)d_in[5], (const float*)d_in[10], (const float*)d_in[15]};
    const float* bt[3] = {(const float*)d_in[6], (const float*)d_in[11], (const float*)d_in[16]};
    int E = in_sizes[1] / 2;

    void *p_h0, *p_h1, *p_wh, *p_wl, *p_st;
    cudaGetSymbolAddress(&p_h0, g_h0);
    cudaGetSymbolAddress(&p_h1, g_h1);
    cudaGetSymbolAddress(&p_wh, g_WtHh);
    cudaGetSymbolAddress(&p_wl, g_WtHl);
    cudaGetSymbolAddress(&p_st, g_stats3);
    __half* h0 = (__half*)p_h0;
    __half* h1 = (__half*)p_h1;
    const uint32_t* Whh = (const uint32_t*)p_wh;
    const uint32_t* Whl = (const uint32_t*)p_wl;
    float* st = (float*)p_st;   // st + L*2*DD

    prep_w_all<<<(3 * 128 * DD + 255) / 256, 256>>>(Wl[0], Wr[0], Wl[1], Wr[1], Wl[2], Wr[2]);
    csr_kernel<<<CSRG, 256>>>(ei, E);

    const int GB = (NN * 32 + 255) / 256;
    const int MBL = (NN + 127) / 128;

    // layer 0: x fp32 -> h0 fp16
    gather_f32<<<GB, 256>>>(x);
    gemm_kernel<float, 0, __half><<<MBL, 128>>>(
        x, Whh, Whl, bl[0], nullptr, nullptr, nullptr, st, h0);

    // layer 1: h0 fp16 -> h1 fp16 (BN0+ReLU fused in consumers)
    gather_f16<<<GB, 256>>>(h0, st, gm[0], bt[0]);
    gemm_kernel<__half, 1, __half><<<MBL, 128>>>(
        h0, Whh + 128 * DD, Whl + 128 * DD, bl[1], st, gm[0], bt[0], st + 2 * DD, h1);

    // layer 2: h1 fp16 -> d_out fp32
    gather_f16<<<GB, 256>>>(h1, st + 2 * DD, gm[1], bt[1]);
    gemm_kernel<__half, 1, float><<<MBL, 128>>>(
        h1, Whh + 2 * 128 * DD, Whl + 2 * 128 * DD, bl[2],
        st + 2 * DD, gm[1], bt[1], st + 4 * DD, (float*)d_out);

    apply_kernel<<<(NN * DD / 4 + 255) / 256, 256>>>((float*)d_out, st + 4 * DD, gm[2], bt[2]);
}

// round 16
// speedup vs baseline: 1.1387x; 1.1387x over previous
#include <cuda_runtime.h>
#include <cuda_fp16.h>
#include <cstdint>
#include <type_traits>

#define NN 50000
#define DD 128
#define K2 256
#define EE 800000
#define EPS 1e-5f

// ---------------- scratch (device globals) ----------------------------------
__device__ float  g_agg[NN * DD];
__device__ __half g_h0[NN * DD];
__device__ __half g_h1[NN * DD];
__device__ uint32_t g_WtHh[3 * 128 * DD];  // all weights: fp16-hi half2 pairs over k
__device__ uint32_t g_WtHl[3 * 128 * DD];  // fp16-lo residual pairs
__device__ float  g_stats[4 * DD];         // [sum | sumsq | scale | shift]
__device__ int    g_deg[NN];
__device__ int    g_rowptr[NN + 1];
__device__ int    g_cursor[NN];
__device__ int    g_col[EE];
__device__ int    g_bsum[64];
__device__ int    g_scan_count;

// ---------------- CSR build --------------------------------------------------
__global__ void count_kernel(const int* __restrict__ ei, int E) {
    int e = blockIdx.x * blockDim.x + threadIdx.x;
    if (e < E) {
        int d = ei[E + e];
        if (d >= 0 && d < NN) atomicAdd(&g_deg[d], 1);
    }
}

__global__ void scan_fused_kernel() {
    __shared__ int wsum[32];
    __shared__ int s_off;
    int t = threadIdx.x, b = blockIdx.x;
    int idx = b * 1024 + t;
    int wid = t >> 5, lane = t & 31;
    int v = (idx < NN) ? g_deg[idx] : 0;
    int incl = v;
#pragma unroll
    for (int off = 1; off < 32; off <<= 1) {
        int y = __shfl_up_sync(0xffffffffu, incl, off);
        if (lane >= off) incl += y;
    }
    if (lane == 31) wsum[wid] = incl;
    __syncthreads();
    if (wid == 0) {
        int si = wsum[lane];
#pragma unroll
        for (int off = 1; off < 32; off <<= 1) {
            int y = __shfl_up_sync(0xffffffffu, si, off);
            if (lane >= off) si += y;
        }
        wsum[lane] = si;
    }
    __syncthreads();
    int total = wsum[31];
    if (t == 0) {
        g_bsum[b] = total;
        __threadfence();
        atomicAdd(&g_scan_count, 1);
        while (atomicAdd(&g_scan_count, 0) < (int)gridDim.x) {}
        __threadfence();
        int off = 0;
        for (int j = 0; j < b; j++) off += g_bsum[j];
        s_off = off;
    }
    __syncthreads();
    int woff = (wid > 0) ? wsum[wid - 1] : 0;
    if (idx < NN) {
        int r = s_off + woff + incl - v;
        g_rowptr[idx] = r;
        g_cursor[idx] = r;
    }
    if (b == gridDim.x - 1 && t == 0) g_rowptr[NN] = s_off + total;
}

__global__ void fill_kernel(const int* __restrict__ ei, int E) {
    int e = blockIdx.x * blockDim.x + threadIdx.x;
    if (e < E) {
        int s = ei[e];
        int d = ei[E + e];
        if (d >= 0 && d < NN) {
            int pos = atomicAdd(&g_cursor[d], 1);
            g_col[pos] = s;
        }
    }
}

// ---------------- gather (fp32 input, layer 0) + zero BN accumulators --------
__global__ void gather_f32(const float* __restrict__ x) {
    if (blockIdx.x == 0 && threadIdx.x < 2 * DD) g_stats[threadIdx.x] = 0.f;
    int w = (blockIdx.x * blockDim.x + threadIdx.x) >> 5;
    int lane = threadIdx.x & 31;
    if (w >= NN) return;
    int start = g_rowptr[w], end = g_rowptr[w + 1];
    float4 acc = make_float4(0.f, 0.f, 0.f, 0.f);
    int i = start;
    for (; i + 7 < end; i += 8) {
        int sidx[8];
#pragma unroll
        for (int u = 0; u < 8; u++) sidx[u] = __ldg(&g_col[i + u]);
        float4 vv[8];
#pragma unroll
        for (int u = 0; u < 8; u++)
            vv[u] = __ldg((const float4*)(x + (size_t)sidx[u] * DD) + lane);
#pragma unroll
        for (int u = 0; u < 8; u++) {
            acc.x += vv[u].x; acc.y += vv[u].y;
            acc.z += vv[u].z; acc.w += vv[u].w;
        }
    }
    for (; i < end; i++) {
        int s = __ldg(&g_col[i]);
        float4 v = __ldg((const float4*)(x + (size_t)s * DD) + lane);
        acc.x += v.x; acc.y += v.y; acc.z += v.z; acc.w += v.w;
    }
    float sc = 1.0f / fmaxf((float)(end - start), 1.0f);
    acc.x *= sc; acc.y *= sc; acc.z *= sc; acc.w *= sc;
    ((float4*)(g_agg + (size_t)w * DD))[lane] = acc;
}

// ---------------- gather (fp16 input + fused BN+ReLU), layers 1/2 -----------
__global__ void gather_f16(const __half* __restrict__ x) {
    if (blockIdx.x == 0 && threadIdx.x < 2 * DD) g_stats[threadIdx.x] = 0.f;
    int w = (blockIdx.x * blockDim.x + threadIdx.x) >> 5;
    int lane = threadIdx.x & 31;
    if (w >= NN) return;
    float4 s4 = ((const float4*)(g_stats + 2 * DD))[lane];
    float4 b4 = ((const float4*)(g_stats + 3 * DD))[lane];
    int start = g_rowptr[w], end = g_rowptr[w + 1];
    float4 acc = make_float4(0.f, 0.f, 0.f, 0.f);

    auto addv = [&](uint2 raw) {
        __half2 h0 = *reinterpret_cast<__half2*>(&raw.x);
        __half2 h1 = *reinterpret_cast<__half2*>(&raw.y);
        float2 f0 = __half22float2(h0);
        float2 f1 = __half22float2(h1);
        acc.x += fmaxf(fmaf(f0.x, s4.x, b4.x), 0.f);
        acc.y += fmaxf(fmaf(f0.y, s4.y, b4.y), 0.f);
        acc.z += fmaxf(fmaf(f1.x, s4.z, b4.z), 0.f);
        acc.w += fmaxf(fmaf(f1.y, s4.w, b4.w), 0.f);
    };

    int i = start;
    for (; i + 7 < end; i += 8) {
        int sidx[8];
#pragma unroll
        for (int u = 0; u < 8; u++) sidx[u] = __ldg(&g_col[i + u]);
        uint2 rr[8];
#pragma unroll
        for (int u = 0; u < 8; u++)
            rr[u] = __ldg((const uint2*)(x + (size_t)sidx[u] * DD) + lane);
#pragma unroll
        for (int u = 0; u < 8; u++) addv(rr[u]);
    }
    for (; i < end; i++) {
        int s = __ldg(&g_col[i]);
        addv(__ldg((const uint2*)(x + (size_t)s * DD) + lane));
    }
    float sc = 1.0f / fmaxf((float)(end - start), 1.0f);
    acc.x *= sc; acc.y *= sc; acc.z *= sc; acc.w *= sc;
    ((float4*)(g_agg + (size_t)w * DD))[lane] = acc;
}

// ---------------- weight prep: fp16 hi/lo pairs for ALL k --------------------
__global__ void prep_w_all(const float* __restrict__ Wl0, const float* __restrict__ Wr0,
                           const float* __restrict__ Wl1, const float* __restrict__ Wr1,
                           const float* __restrict__ Wl2, const float* __restrict__ Wr2) {
    int i = blockIdx.x * blockDim.x + threadIdx.x;
    if (i == 0) g_scan_count = 0;
    if (i < NN / 4) ((int4*)g_deg)[i] = make_int4(0, 0, 0, 0);
    if (i >= 3 * 128 * DD) return;
    int L = i / (128 * DD);
    int rem = i - L * (128 * DD);
    int p = rem >> 7, n = rem & 127;
    const float* Wl = (L == 0) ? Wl0 : (L == 1 ? Wl1 : Wl2);
    const float* Wr = (L == 0) ? Wr0 : (L == 1 ? Wr1 : Wr2);
    int k0 = 2 * p;
    float w0, w1;
    if (k0 < DD) {
        w0 = __ldg(&Wl[n * DD + k0]);
        w1 = __ldg(&Wl[n * DD + k0 + 1]);
    } else {
        w0 = __ldg(&Wr[n * DD + (k0 - DD)]);
        w1 = __ldg(&Wr[n * DD + (k0 - DD) + 1]);
    }
    __half h0 = __float2half_rn(w0);
    __half h1 = __float2half_rn(w1);
    __half l0 = __float2half_rn(w0 - __half2float(h0));
    __half l1 = __float2half_rn(w1 - __half2float(h1));
    __half2 hh = __halves2half2(h0, h1);
    __half2 ll = __halves2half2(l0, l1);
    g_WtHh[i] = *reinterpret_cast<uint32_t*>(&hh);
    g_WtHl[i] = *reinterpret_cast<uint32_t*>(&ll);
}

// ---------------- GEMM: fp16 hi/lo 3-term, 256 threads (8 warps, 2x4) --------
#define AHSTRIDE 12
#define BHSTRIDE 136

__device__ __forceinline__ void split_f16x2(float a, float b, uint32_t& hi, uint32_t& lo) {
    __half ha = __float2half_rn(a), hb = __float2half_rn(b);
    __half la = __float2half_rn(a - __half2float(ha));
    __half lb = __float2half_rn(b - __half2float(hb));
    __half2 h = __halves2half2(ha, hb);
    __half2 l = __halves2half2(la, lb);
    hi = *reinterpret_cast<uint32_t*>(&h);
    lo = *reinterpret_cast<uint32_t*>(&l);
}

__device__ __forceinline__ void mma_f16(float* d, uint32_t a0, uint32_t a1,
                                        uint32_t a2, uint32_t a3,
                                        uint32_t b0, uint32_t b1) {
    asm volatile(
        "mma.sync.aligned.m16n8k16.row.col.f32.f16.f16.f32 "
        "{%0,%1,%2,%3},{%4,%5,%6,%7},{%8,%9},{%0,%1,%2,%3};"
        : "+f"(d[0]), "+f"(d[1]), "+f"(d[2]), "+f"(d[3])
        : "r"(a0), "r"(a1), "r"(a2), "r"(a3), "r"(b0), "r"(b1));
}

// TI: input type; XFORM: apply BN+ReLU (g_stats affine) to x-half; TO: output
template <typename TI, int XFORM, typename TO>
__global__ __launch_bounds__(256, 2)
void gemm_kernel(const TI* __restrict__ Xin,
                 const uint32_t* __restrict__ WtHh,
                 const uint32_t* __restrict__ WtHl,
                 const float* __restrict__ bias,
                 TO* __restrict__ Y) {
    constexpr bool USE_H = std::is_same_v<TI, __half>;

    __shared__ __align__(16) uint32_t AshH[128 * AHSTRIDE];
    __shared__ __align__(16) uint32_t AshL[128 * AHSTRIDE];
    __shared__ __align__(16) uint32_t BshH[8 * BHSTRIDE];
    __shared__ __align__(16) uint32_t BshL[8 * BHSTRIDE];
    __shared__ float bias_s[128];
    __shared__ float sc_s[128];
    __shared__ float sh_s[128];

    int tid = threadIdx.x;
    int brow = blockIdx.x * 128;
    int wid = tid >> 5, lane = tid & 31;
    int group = lane >> 2, tg = lane & 3;
    int warp_m = (wid >> 2) * 64;       // 0 or 64
    int warp_n = (wid & 3) * 32;        // 0, 32, 64, 96

    if (tid < 128) {
        bias_s[tid] = __ldg(&bias[tid]);
        if (XFORM) {
            sc_s[tid] = __ldg(&g_stats[2 * DD + tid]);
            sh_s[tid] = __ldg(&g_stats[3 * DD + tid]);
        }
    }
    __syncthreads();

    float acc[4][4][4];
#pragma unroll
    for (int mt = 0; mt < 4; mt++)
#pragma unroll
        for (int nt = 0; nt < 4; nt++)
#pragma unroll
            for (int c = 0; c < 4; c++) acc[mt][nt][c] = 0.f;

    float4 pa[2];
    uint2 pbh[2], pbl[2];

    auto load_tiles = [&](int kc) {
#pragma unroll
        for (int i = 0; i < 2; i++) {
            int l = tid + i * 256;
            int row = l >> 2, kq = l & 3;
            int r = brow + row;
            float4 v = make_float4(0.f, 0.f, 0.f, 0.f);
            if (r < NN) {
                if (kc < DD) {
                    v = __ldg((const float4*)(g_agg + (size_t)r * DD + kc) + kq);
                } else {
                    int kg = (kc - DD) + kq * 4;
                    if constexpr (USE_H) {
                        uint2 raw = __ldg((const uint2*)(Xin + (size_t)r * DD + kg));
                        __half2 ha = *reinterpret_cast<__half2*>(&raw.x);
                        __half2 hb = *reinterpret_cast<__half2*>(&raw.y);
                        float2 f0 = __half22float2(ha);
                        float2 f1 = __half22float2(hb);
                        v = make_float4(f0.x, f0.y, f1.x, f1.y);
                    } else {
                        v = __ldg((const float4*)(Xin + (size_t)r * DD + kg));
                    }
                    if (XFORM) {
                        float4 s4 = *(const float4*)(sc_s + kg);
                        float4 b4 = *(const float4*)(sh_s + kg);
                        v.x = fmaxf(fmaf(v.x, s4.x, b4.x), 0.f);
                        v.y = fmaxf(fmaf(v.y, s4.y, b4.y), 0.f);
                        v.z = fmaxf(fmaf(v.z, s4.z, b4.z), 0.f);
                        v.w = fmaxf(fmaf(v.w, s4.w, b4.w), 0.f);
                    }
                }
            }
            pa[i] = v;
        }
        int p0 = kc >> 1;
#pragma unroll
        for (int i = 0; i < 2; i++) {
            int l = tid + i * 256;
            int p = l >> 6, j2 = l & 63;
            pbh[i] = ((const uint2*)WtHh)[(size_t)(p0 + p) * 64 + j2];
            pbl[i] = ((const uint2*)WtHl)[(size_t)(p0 + p) * 64 + j2];
        }
    };

    auto store_tiles = [&]() {
#pragma unroll
        for (int i = 0; i < 2; i++) {
            int l = tid + i * 256;
            int row = l >> 2, kq = l & 3;
            uint32_t h0, l0, h1, l1;
            split_f16x2(pa[i].x, pa[i].y, h0, l0);
            split_f16x2(pa[i].z, pa[i].w, h1, l1);
            *(uint2*)&AshH[row * AHSTRIDE + kq * 2] = make_uint2(h0, h1);
            *(uint2*)&AshL[row * AHSTRIDE + kq * 2] = make_uint2(l0, l1);
        }
#pragma unroll
        for (int i = 0; i < 2; i++) {
            int l = tid + i * 256;
            int p = l >> 6, j2 = l & 63;
            *(uint2*)&BshH[p * BHSTRIDE + j2 * 2] = pbh[i];
            *(uint2*)&BshL[p * BHSTRIDE + j2 * 2] = pbl[i];
        }
    };

    load_tiles(0);

    for (int kc = 0; kc < K2; kc += 16) {
        store_tiles();
        __syncthreads();
        if (kc + 16 < K2) load_tiles(kc + 16);

        uint32_t fbh0[4], fbh1[4], fbl0[4], fbl1[4];
#pragma unroll
        for (int nt = 0; nt < 4; nt++) {
            int n = warp_n + nt * 8 + group;
            fbh0[nt] = BshH[tg * BHSTRIDE + n];
            fbh1[nt] = BshH[(tg + 4) * BHSTRIDE + n];
            fbl0[nt] = BshL[tg * BHSTRIDE + n];
            fbl1[nt] = BshL[(tg + 4) * BHSTRIDE + n];
        }
#pragma unroll
        for (int mt = 0; mt < 4; mt++) {
            int m = warp_m + mt * 16;
            uint32_t ah0 = AshH[(m + group) * AHSTRIDE + tg];
            uint32_t ah1 = AshH[(m + group + 8) * AHSTRIDE + tg];
            uint32_t ah2 = AshH[(m + group) * AHSTRIDE + tg + 4];
            uint32_t ah3 = AshH[(m + group + 8) * AHSTRIDE + tg + 4];
            uint32_t al0 = AshL[(m + group) * AHSTRIDE + tg];
            uint32_t al1 = AshL[(m + group + 8) * AHSTRIDE + tg];
            uint32_t al2 = AshL[(m + group) * AHSTRIDE + tg + 4];
            uint32_t al3 = AshL[(m + group + 8) * AHSTRIDE + tg + 4];
#pragma unroll
            for (int nt = 0; nt < 4; nt++) {
                mma_f16(acc[mt][nt], ah0, ah1, ah2, ah3, fbh0[nt], fbh1[nt]);
                mma_f16(acc[mt][nt], al0, al1, al2, al3, fbh0[nt], fbh1[nt]);
                mma_f16(acc[mt][nt], ah0, ah1, ah2, ah3, fbl0[nt], fbl1[nt]);
            }
        }
        __syncthreads();
    }

    // ---- epilogue: bias + store + fused BN partial stats ----
    float cs[8], cq[8];
#pragma unroll
    for (int i = 0; i < 8; i++) { cs[i] = 0.f; cq[i] = 0.f; }

#pragma unroll
    for (int mt = 0; mt < 4; mt++) {
        int r0 = brow + warp_m + mt * 16 + group;
        int r1 = r0 + 8;
#pragma unroll
        for (int nt = 0; nt < 4; nt++) {
            int c = warp_n + nt * 8 + 2 * tg;
            float b0 = bias_s[c], b1 = bias_s[c + 1];
            float o0 = acc[mt][nt][0] + b0, o1 = acc[mt][nt][1] + b1;
            float o2 = acc[mt][nt][2] + b0, o3 = acc[mt][nt][3] + b1;
            if (r0 < NN) {
                if constexpr (std::is_same_v<TO, __half>) {
                    *(__half2*)(Y + (size_t)r0 * DD + c) = __floats2half2_rn(o0, o1);
                } else {
                    *(float2*)(Y + (size_t)r0 * DD + c) = make_float2(o0, o1);
                }
                cs[nt * 2 + 0] += o0; cq[nt * 2 + 0] += o0 * o0;
                cs[nt * 2 + 1] += o1; cq[nt * 2 + 1] += o1 * o1;
            }
            if (r1 < NN) {
                if constexpr (std::is_same_v<TO, __half>) {
                    *(__half2*)(Y + (size_t)r1 * DD + c) = __floats2half2_rn(o2, o3);
                } else {
                    *(float2*)(Y + (size_t)r1 * DD + c) = make_float2(o2, o3);
                }
                cs[nt * 2 + 0] += o2; cq[nt * 2 + 0] += o2 * o2;
                cs[nt * 2 + 1] += o3; cq[nt * 2 + 1] += o3 * o3;
            }
        }
    }
#pragma unroll
    for (int i = 0; i < 8; i++) {
#pragma unroll
        for (int off = 4; off < 32; off <<= 1) {
            cs[i] += __shfl_xor_sync(0xffffffffu, cs[i], off);
            cq[i] += __shfl_xor_sync(0xffffffffu, cq[i], off);
        }
    }
    if (group == 0) {
#pragma unroll
        for (int i = 0; i < 8; i++) {
            int c = warp_n + (i >> 1) * 8 + 2 * tg + (i & 1);
            atomicAdd(&g_stats[c], cs[i]);
            atomicAdd(&g_stats[DD + c], cq[i]);
        }
    }
}

// ---------------- BN finalize + final apply ----------------------------------
__global__ void finalize_kernel(const float* __restrict__ gamma,
                                const float* __restrict__ beta) {
    int c = threadIdx.x;
    float m = g_stats[c] * (1.0f / NN);
    float var = g_stats[DD + c] * (1.0f / NN) - m * m;
    float sc = __ldg(&gamma[c]) * rsqrtf(var + EPS);
    g_stats[2 * DD + c] = sc;
    g_stats[3 * DD + c] = __ldg(&beta[c]) - m * sc;
}

__global__ void apply_kernel(float* __restrict__ Y) {
    int i = blockIdx.x * blockDim.x + threadIdx.x;
    if (i >= NN * (DD / 4)) return;
    float4 v = ((float4*)Y)[i];
    int c = (i & (DD / 4 - 1)) * 4;
    float4 s4 = *(const float4*)(g_stats + 2 * DD + c);
    float4 b4 = *(const float4*)(g_stats + 3 * DD + c);
    v.x = fmaf(v.x, s4.x, b4.x);
    v.y = fmaf(v.y, s4.y, b4.y);
    v.z = fmaf(v.z, s4.z, b4.z);
    v.w = fmaf(v.w, s4.w, b4.w);
    ((float4*)Y)[i] = v;
}

// ---------------- launch ----------------------------------------------------
extern "C" void kernel_launch(void* const* d_in, const int* in_sizes, int n_in,
                              void* d_out, int out_size) {
    const float* x = (const float*)d_in[0];
    const int* ei = (const int*)d_in[1];
    const float* Wl[3] = {(const float*)d_in[2], (const float*)d_in[7], (const float*)d_in[12]};
    const float* bl[3] = {(const float*)d_in[3], (const float*)d_in[8], (const float*)d_in[13]};
    const float* Wr[3] = {(const float*)d_in[4], (const float*)d_in[9], (const float*)d_in[14]};
    const float* gm[3] = {(const float*)d_in[5], (const float*)d_in[10], (const float*)d_in[15]};
    const float* bt[3] = {(const float*)d_in[6], (const float*)d_in[11], (const float*)d_in[16]};
    int E = in_sizes[1] / 2;

    void *p_h0, *p_h1, *p_wh, *p_wl;
    cudaGetSymbolAddress(&p_h0, g_h0);
    cudaGetSymbolAddress(&p_h1, g_h1);
    cudaGetSymbolAddress(&p_wh, g_WtHh);
    cudaGetSymbolAddress(&p_wl, g_WtHl);
    __half* h0 = (__half*)p_h0;
    __half* h1 = (__half*)p_h1;
    const uint32_t* Whh = (const uint32_t*)p_wh;
    const uint32_t* Whl = (const uint32_t*)p_wl;

    prep_w_all<<<(3 * 128 * DD + 255) / 256, 256>>>(Wl[0], Wr[0], Wl[1], Wr[1], Wl[2], Wr[2]);

    const int NB = (NN + 1023) / 1024;
    count_kernel<<<(E + 255) / 256, 256>>>(ei, E);
    scan_fused_kernel<<<NB, 1024>>>();
    fill_kernel<<<(E + 255) / 256, 256>>>(ei, E);

    const int GB = (NN * 32 + 255) / 256;
    const int MBL = (NN + 127) / 128;

    // layer 0: x fp32 -> h0 fp16
    gather_f32<<<GB, 256>>>(x);
    gemm_kernel<float, 0, __half><<<MBL, 256>>>(x, Whh, Whl, bl[0], h0);
    finalize_kernel<<<1, 128>>>(gm[0], bt[0]);

    // layer 1: h0 fp16 -> h1 fp16
    gather_f16<<<GB, 256>>>(h0);
    gemm_kernel<__half, 1, __half><<<MBL, 256>>>(
        h0, Whh + 128 * DD, Whl + 128 * DD, bl[1], h1);
    finalize_kernel<<<1, 128>>>(gm[1], bt[1]);

    // layer 2: h1 fp16 -> d_out fp32
    gather_f16<<<GB, 256>>>(h1);
    gemm_kernel<__half, 1, float><<<MBL, 256>>>(
        h1, Whh + 2 * 128 * DD, Whl + 2 * 128 * DD, bl[2], (float*)d_out);
    finalize_kernel<<<1, 128>>>(gm[2], bt[2]);
    apply_kernel<<<(NN * DD / 4 + 255) / 256, 256>>>((float*)d_out);
}